// round 16
// baseline (speedup 1.0000x reference)
#include <cuda_runtime.h>
#include <cuda_fp16.h>
#include <cstdint>

#define B_  16
#define NC_ 10
#define H_  6
#define C_  384
#define HD_ 64
#define T_  197
#define N_  196
#define BH_ (B_*H_)
#define CH_ (NC_*H_)
#define SCALE_ 0.125f
#define KP_ 224

#define OW_QK  0
#define OW_QK2 147456
#define OW_V   294912
#define OW_R   442368
#define OW_1   589824
#define OW_2   1179648
#define WT_TOT 1769472

__device__ float g_n1 [26*C_];
__device__ __align__(16) __half g_n2[26*N_*C_];
__device__ float g_qv [NC_*2*C_];
__device__ float g_k  [B_*C_];
__device__ float g_attn[B_*CH_];
__device__ float g_ctx[B_*C_];
__device__ __align__(16) __half g_qq [2*BH_*N_*HD_];   // qh | q2
__device__ __align__(16) __half g_akk[2*CH_*N_*HD_];   // kh | k2
__device__ __align__(16) __half g_vrT[BH_*HD_*KP_];
__device__ __align__(16) __half g_tmp[BH_*N_*KP_];
__device__ __align__(16) __half g_rectH[B_*N_*C_];
__device__ float g_xx [B_*T_*C_];
__device__ __align__(16) __half g_hdn[B_*T_*C_];
__device__ __align__(16) __half g_h1 [B_*T_*4*C_];
__device__ __align__(16) __half g_wt [WT_TOT];

#define U32(x) __float_as_uint(x)

__device__ __forceinline__ void mma16h(float* c, uint32_t a0, uint32_t a1, uint32_t a2, uint32_t a3,
                                       uint32_t b0, uint32_t b1)
{
    asm volatile("mma.sync.aligned.m16n8k16.row.col.f32.f16.f16.f32 "
                 "{%0,%1,%2,%3},{%4,%5,%6,%7},{%8,%9},{%0,%1,%2,%3};\n"
                 : "+f"(c[0]), "+f"(c[1]), "+f"(c[2]), "+f"(c[3])
                 : "r"(a0), "r"(a1), "r"(a2), "r"(a3), "r"(b0), "r"(b1));
}

__device__ __forceinline__ uint32_t pack_hf2(float lo, float hi) {
    uint32_t d;
    asm("cvt.rn.f16x2.f32 %0, %1, %2;" : "=r"(d) : "f"(hi), "f"(lo));
    return d;
}

__device__ __forceinline__ void cp16(uint32_t dst, const void* src, bool p) {
    int sz = p ? 16 : 0;
    asm volatile("cp.async.cg.shared.global [%0], [%1], 16, %2;" :: "r"(dst), "l"(src), "r"(sz));
}

__device__ __forceinline__ float gelu_f(float x) {
    return 0.5f * x * (1.f + erff(x * 0.7071067811865475f));
}

__device__ __forceinline__ size_t omap(int mode, int r, int c, int N, int bz)
{
    if (mode == 0) return (size_t)r * N + c;
    if (mode == 1) {
        int bq = r / N_, n = r % N_;
        return ((size_t)(bq*H_ + (c >> 6)) * N_ + n) * HD_ + (c & 63);
    }
    if (mode == 2) {
        int bq = r / N_, n = r % N_;
        return ((size_t)bq*T_ + 1 + n) * C_ + c;
    }
    if (mode == 4) {
        int bq = r / N_, n = r % N_;
        return ((size_t)(bq*H_ + (c >> 6)) * HD_ + (c & 63)) * KP_ + n;
    }
    return ((size_t)bz * N_ + r) * HD_ + c; // 5
}

// ---------------- merged weight transpose-convert ----------------
__global__ void transpose_all(const float* __restrict__ Wqk, const float* __restrict__ Wqk2,
                              const float* __restrict__ Wv,  const float* __restrict__ Wr,
                              const float* __restrict__ W1,  const float* __restrict__ W2,
                              __half* __restrict__ wt)
{
    __shared__ float tile[32][33];
    int bid = blockIdx.x;
    const float* src; __half* dst; int K, N, tn;
    if      (bid < 144)  { src = Wqk;  dst = wt + OW_QK;  K = C_;   N = C_;   tn = bid; }
    else if (bid < 288)  { src = Wqk2; dst = wt + OW_QK2; K = C_;   N = C_;   tn = bid - 144; }
    else if (bid < 432)  { src = Wv;   dst = wt + OW_V;   K = C_;   N = C_;   tn = bid - 288; }
    else if (bid < 576)  { src = Wr;   dst = wt + OW_R;   K = C_;   N = C_;   tn = bid - 432; }
    else if (bid < 1152) { src = W1;   dst = wt + OW_1;   K = C_;   N = 4*C_; tn = bid - 576; }
    else                 { src = W2;   dst = wt + OW_2;   K = 4*C_; N = C_;   tn = bid - 1152; }
    int ntx = N >> 5;
    int nb = (tn % ntx) * 32, kb = (tn / ntx) * 32;
    int tx = threadIdx.x, ty = threadIdx.y;
#pragma unroll
    for (int i = 0; i < 32; i += 8)
        tile[ty + i][tx] = src[(size_t)(kb + ty + i) * N + nb + tx];
    __syncthreads();
#pragma unroll
    for (int i = 0; i < 32; i += 8)
        dst[(size_t)(nb + ty + i) * K + kb + tx] = __float2half(tile[tx][ty + i]);
}

__global__ void zero_pads(__half* __restrict__ tmp, __half* __restrict__ vrT)
{
    int row = blockIdx.x;
    int t = threadIdx.x;
    if (t >= KP_ - N_) return;
    if (row < BH_*N_) tmp[(size_t)row*KP_ + N_ + t] = __float2half(0.f);
    else {
        int r2 = row - BH_*N_;
        vrT[(size_t)r2*KP_ + N_ + t] = __float2half(0.f);
    }
}

// ---------------- LayerNorm ----------------
__global__ void ln_kernel(const float* __restrict__ in, void* __restrict__ outv,
                          const float* __restrict__ g, const float* __restrict__ bt,
                          int rows, int inner, long outer_stride, long inner_stride, int h16)
{
    int row = blockIdx.x;
    if (row >= rows) return;
    const float* src = in + (long)(row / inner) * outer_stride + (long)(row % inner) * inner_stride;
    int t = threadIdx.x;
    float v[3]; float s = 0.f;
#pragma unroll
    for (int i = 0; i < 3; i++) { v[i] = src[t + i*128]; s += v[i]; }
    __shared__ float red[4];
#pragma unroll
    for (int o = 16; o > 0; o >>= 1) s += __shfl_xor_sync(0xffffffffu, s, o);
    if ((t & 31) == 0) red[t >> 5] = s;
    __syncthreads();
    float mean = (red[0] + red[1] + red[2] + red[3]) * (1.f/384.f);
    float q = 0.f;
#pragma unroll
    for (int i = 0; i < 3; i++) { float d = v[i] - mean; q += d*d; }
#pragma unroll
    for (int o = 16; o > 0; o >>= 1) q += __shfl_xor_sync(0xffffffffu, q, o);
    __syncthreads();
    if ((t & 31) == 0) red[t >> 5] = q;
    __syncthreads();
    float var = (red[0] + red[1] + red[2] + red[3]) * (1.f/384.f);
    float rs = rsqrtf(var + 1e-5f);
#pragma unroll
    for (int i = 0; i < 3; i++) {
        int c = t + i*128;
        float o = (v[i] - mean) * rs * g[c] + bt[c];
        if (h16) ((__half*)outv)[(long)row*C_ + c] = __float2half(o);
        else     ((float*)outv)[(long)row*C_ + c] = o;
    }
}

// ---------------- merged cls qv/k row GEMM ----------------
__global__ __launch_bounds__(256)
void rowgemm_cls(const float* __restrict__ n1, const float* __restrict__ Wqv,
                 const float* __restrict__ Wk, float* __restrict__ qv, float* __restrict__ kb)
{
    __shared__ float a_s[384];
    __shared__ float part[256];
    int bx = blockIdx.x, by = blockIdx.y;
    const float* A; const float* W; float* out; int N;
    if (bx < NC_) { A = n1 + (16+bx)*C_; W = Wqv; out = qv + bx*2*C_; N = 2*C_; }
    else {
        if (by >= 6) return;
        A = n1 + (bx-NC_)*C_; W = Wk; out = kb + (bx-NC_)*C_; N = C_;
    }
    int cb = by * 64;
    int t = threadIdx.x;
    for (int i = t; i < 384; i += 256) a_s[i] = A[i];
    __syncthreads();
    int col = t & 63, sp = t >> 6;
    int base = sp * 96;
    float s0 = 0.f, s1 = 0.f;
    const float* Wp = W + (size_t)base*N + cb + col;
#pragma unroll 8
    for (int k = 0; k < 96; k += 2) {
        s0 += a_s[base+k]   * Wp[(size_t)(k)*N];
        s1 += a_s[base+k+1] * Wp[(size_t)(k+1)*N];
    }
    part[t] = s0 + s1;
    __syncthreads();
    if (t < 64) out[cb + t] = part[t] + part[64+t] + part[128+t] + part[192+t];
}

__global__ __launch_bounds__(256)
void rowgemm(const float* __restrict__ A, const float* __restrict__ W,
             const float* __restrict__ bias, float* __restrict__ out,
             int N, long out_stride)
{
    __shared__ float a_s[384];
    __shared__ float part[256];
    int row = blockIdx.x, cb = blockIdx.y * 64;
    int t = threadIdx.x;
    for (int i = t; i < 384; i += 256) a_s[i] = A[(size_t)row*384 + i];
    __syncthreads();
    int col = t & 63, sp = t >> 6;
    int base = sp * 96;
    float s0 = 0.f, s1 = 0.f;
    const float* Wp = W + (size_t)base*N + cb + col;
#pragma unroll 8
    for (int k = 0; k < 96; k += 2) {
        s0 += a_s[base+k]   * Wp[(size_t)(k)*N];
        s1 += a_s[base+k+1] * Wp[(size_t)(k+1)*N];
    }
    part[t] = s0 + s1;
    __syncthreads();
    if (t < 64) {
        float v = part[t] + part[64+t] + part[128+t] + part[192+t];
        if (bias) v += bias[cb + t];
        out[(size_t)row*out_stride + cb + t] = v;
    }
}

// ---------------- cls attention ----------------
__global__ void attn_cls_kernel(const float* __restrict__ qv, const float* __restrict__ k,
                                float* __restrict__ attn, float* __restrict__ ctx)
{
    int b = blockIdx.x, t = threadIdx.x;
    __shared__ float sl[CH_];
    if (t < CH_) {
        int n = t / H_, h = t % H_;
        float s = 0.f;
        for (int d = 0; d < HD_; d++) s += qv[n*2*C_ + h*HD_ + d] * k[b*C_ + h*HD_ + d];
        sl[t] = s * SCALE_;
    }
    __syncthreads();
    if (t < H_) {
        float mx = -1e30f;
        for (int n = 0; n < NC_; n++) mx = fmaxf(mx, sl[n*H_ + t]);
        float sum = 0.f;
        for (int n = 0; n < NC_; n++) { float e = expf(sl[n*H_ + t] - mx); sl[n*H_ + t] = e; sum += e; }
        float inv = 1.f / sum;
        for (int n = 0; n < NC_; n++) { sl[n*H_ + t] *= inv; attn[b*CH_ + n*H_ + t] = sl[n*H_ + t]; }
    }
    __syncthreads();
    {
        int h = t >> 6, d = t & 63;
        float s = 0.f;
        for (int n = 0; n < NC_; n++) s += sl[n*H_ + h] * qv[n*2*C_ + C_ + h*HD_ + d];
        ctx[b*C_ + t] = s;
    }
}

// ---------------- all-fp16 GEMM, 128-row M tile ----------------
__global__ __launch_bounds__(256, 2)
void gemm_h(const __half* __restrict__ A, const __half* __restrict__ Bt,
            const float* __restrict__ bias, const float* __restrict__ res,
            float* __restrict__ outF, __half* __restrict__ outH,
            int M, int N, int K, int lda, int ldb, int act, int mode,
            long zA, long zB, long zO)
{
    __shared__ __align__(16) __half As[2][128*40];
    __shared__ __align__(16) __half Bs[2][64*40];
    A  += (size_t)blockIdx.z * zA;
    Bt += (size_t)blockIdx.z * zB;
    if (outH) outH += (size_t)blockIdx.z * zO;
    else if (outF) outF += (size_t)blockIdx.z * zO;

    int tid = threadIdx.x;
    int lane = tid & 31, warp = tid >> 5;
    int gid = lane >> 2, tig = lane & 3;
    int wm = warp >> 1, wn = warp & 1;
    int m0 = blockIdx.y * 128, n0 = blockIdx.x * 64;

    int ar = tid >> 1, ac = (tid & 1) * 16;
    int br = tid >> 2, bc = (tid & 3) * 8;

    uint32_t aB[2], bB[2];
#pragma unroll
    for (int s = 0; s < 2; s++) {
        aB[s] = (uint32_t)__cvta_generic_to_shared(&As[s][0]);
        bB[s] = (uint32_t)__cvta_generic_to_shared(&Bs[s][0]);
    }

    bool okA = (m0 + ar < M);
    int nk = K >> 5;

#define GISSUE(it_, st_) do { \
    int kk = (it_) * 32; \
    const __half* sa = A + (size_t)(m0 + ar) * lda + kk + ac; \
    cp16(aB[st_] + (ar*40 + ac)*2,      okA ? sa : (const __half*)A,       okA); \
    cp16(aB[st_] + (ar*40 + ac)*2 + 16, okA ? (sa + 8) : (const __half*)A, okA); \
    cp16(bB[st_] + (br*40 + bc)*2, Bt + (size_t)(n0 + br) * ldb + kk + bc, true); \
    asm volatile("cp.async.commit_group;" ::: "memory"); \
} while (0)

    float acc[2][4][4];
#pragma unroll
    for (int t = 0; t < 2; t++)
#pragma unroll
        for (int u = 0; u < 4; u++)
#pragma unroll
            for (int e = 0; e < 4; e++) acc[t][u][e] = 0.f;

    GISSUE(0, 0);

    for (int it = 0; it < nk; it++) {
        asm volatile("cp.async.wait_group 0;" ::: "memory");
        __syncthreads();
        int st = it & 1;
        if (it + 1 < nk) GISSUE(it + 1, st ^ 1);
        const __half* Af = As[st];
        const __half* Bf = Bs[st];
#pragma unroll
        for (int ks = 0; ks < 2; ks++) {
            int ko = ks * 16;
            uint32_t a[2][4];
#pragma unroll
            for (int t = 0; t < 2; t++) {
                int mb = wm*32 + t*16;
                a[t][0] = *(const uint32_t*)(Af + (mb+gid)*40   + ko + 2*tig);
                a[t][1] = *(const uint32_t*)(Af + (mb+gid+8)*40 + ko + 2*tig);
                a[t][2] = *(const uint32_t*)(Af + (mb+gid)*40   + ko + 2*tig + 8);
                a[t][3] = *(const uint32_t*)(Af + (mb+gid+8)*40 + ko + 2*tig + 8);
            }
#pragma unroll
            for (int u = 0; u < 4; u++) {
                int cb = wn*32 + u*8;
                uint32_t b0 = *(const uint32_t*)(Bf + (cb+gid)*40 + ko + 2*tig);
                uint32_t b1 = *(const uint32_t*)(Bf + (cb+gid)*40 + ko + 2*tig + 8);
                mma16h(acc[0][u], a[0][0],a[0][1],a[0][2],a[0][3], b0,b1);
                mma16h(acc[1][u], a[1][0],a[1][1],a[1][2],a[1][3], b0,b1);
            }
        }
    }
#undef GISSUE

    int bz = blockIdx.z;
#pragma unroll
    for (int t = 0; t < 2; t++) {
#pragma unroll
        for (int u = 0; u < 4; u++) {
            int rb = m0 + wm*32 + t*16 + gid;
            int cb = n0 + wn*32 + u*8 + 2*tig;
#pragma unroll
            for (int e = 0; e < 4; e++) {
                int r = rb + (e >> 1) * 8;
                int c = cb + (e & 1);
                if (r >= M) continue;
                float v = acc[t][u][e];
                if (bias) v += bias[c];
                if (act) v = gelu_f(v);
                size_t idx = omap(mode, r, c, N, bz);
                if (outH) outH[idx] = __float2half(v);
                else {
                    if (res) v += res[idx];
                    outF[idx] = v;
                }
            }
        }
    }
}

// ---------------- all-fp16 GEMM, 64-row M tile (2x4 warps, occ 3) ----------------
__global__ __launch_bounds__(256, 3)
void gemm_h64(const __half* __restrict__ A, const __half* __restrict__ Bt,
              const float* __restrict__ bias, const float* __restrict__ res,
              float* __restrict__ outF, __half* __restrict__ outH,
              int M, int N, int K, int lda, int ldb, int act, int mode,
              long zA, long zB, long zO)
{
    __shared__ __align__(16) __half As[2][64*40];
    __shared__ __align__(16) __half Bs[2][64*40];
    A  += (size_t)blockIdx.z * zA;
    Bt += (size_t)blockIdx.z * zB;
    if (outH) outH += (size_t)blockIdx.z * zO;
    else if (outF) outF += (size_t)blockIdx.z * zO;

    int tid = threadIdx.x;
    int lane = tid & 31, warp = tid >> 5;
    int gid = lane >> 2, tig = lane & 3;
    int wm = warp >> 2, wn = warp & 3;
    int m0 = blockIdx.y * 64, n0 = blockIdx.x * 64;

    int ar = tid >> 2, ac = (tid & 3) * 8;
    int br = tid >> 2, bc = (tid & 3) * 8;

    uint32_t aB[2], bB[2];
#pragma unroll
    for (int s = 0; s < 2; s++) {
        aB[s] = (uint32_t)__cvta_generic_to_shared(&As[s][0]);
        bB[s] = (uint32_t)__cvta_generic_to_shared(&Bs[s][0]);
    }

    bool okA = (m0 + ar < M);
    int nk = K >> 5;

#define GISSUE64(it_, st_) do { \
    int kk = (it_) * 32; \
    const __half* sa = A + (size_t)(m0 + ar) * lda + kk + ac; \
    cp16(aB[st_] + (ar*40 + ac)*2, okA ? sa : (const __half*)A, okA); \
    cp16(bB[st_] + (br*40 + bc)*2, Bt + (size_t)(n0 + br) * ldb + kk + bc, true); \
    asm volatile("cp.async.commit_group;" ::: "memory"); \
} while (0)

    float acc[2][2][4];
#pragma unroll
    for (int t = 0; t < 2; t++)
#pragma unroll
        for (int u = 0; u < 2; u++)
#pragma unroll
            for (int e = 0; e < 4; e++) acc[t][u][e] = 0.f;

    GISSUE64(0, 0);

    for (int it = 0; it < nk; it++) {
        asm volatile("cp.async.wait_group 0;" ::: "memory");
        __syncthreads();
        int st = it & 1;
        if (it + 1 < nk) GISSUE64(it + 1, st ^ 1);
        const __half* Af = As[st];
        const __half* Bf = Bs[st];
#pragma unroll
        for (int ks = 0; ks < 2; ks++) {
            int ko = ks * 16;
            uint32_t a[2][4];
#pragma unroll
            for (int t = 0; t < 2; t++) {
                int mb = wm*32 + t*16;
                a[t][0] = *(const uint32_t*)(Af + (mb+gid)*40   + ko + 2*tig);
                a[t][1] = *(const uint32_t*)(Af + (mb+gid+8)*40 + ko + 2*tig);
                a[t][2] = *(const uint32_t*)(Af + (mb+gid)*40   + ko + 2*tig + 8);
                a[t][3] = *(const uint32_t*)(Af + (mb+gid+8)*40 + ko + 2*tig + 8);
            }
#pragma unroll
            for (int u = 0; u < 2; u++) {
                int cb = wn*16 + u*8;
                uint32_t b0 = *(const uint32_t*)(Bf + (cb+gid)*40 + ko + 2*tig);
                uint32_t b1 = *(const uint32_t*)(Bf + (cb+gid)*40 + ko + 2*tig + 8);
                mma16h(acc[0][u], a[0][0],a[0][1],a[0][2],a[0][3], b0,b1);
                mma16h(acc[1][u], a[1][0],a[1][1],a[1][2],a[1][3], b0,b1);
            }
        }
    }
#undef GISSUE64

    int bz = blockIdx.z;
#pragma unroll
    for (int t = 0; t < 2; t++) {
#pragma unroll
        for (int u = 0; u < 2; u++) {
            int rb = m0 + wm*32 + t*16 + gid;
            int cb = n0 + wn*16 + u*8 + 2*tig;
#pragma unroll
            for (int e = 0; e < 4; e++) {
                int r = rb + (e >> 1) * 8;
                int c = cb + (e & 1);
                if (r >= M) continue;
                float v = acc[t][u][e];
                if (bias) v += bias[c];
                if (act) v = gelu_f(v);
                size_t idx = omap(mode, r, c, N, bz);
                if (outH) outH[idx] = __float2half(v);
                else {
                    if (res) v += res[idx];
                    outF[idx] = v;
                }
            }
        }
    }
}

// ---------------- fused rectified attention core: single-sync, skewed G3 ----------
__global__ __launch_bounds__(256, 2)
void fused_attn5(const __half* __restrict__ qh, const __half* __restrict__ kh,
                 const __half* __restrict__ q2, const __half* __restrict__ k2,
                 const float* __restrict__ w2all, __half* __restrict__ tmp_out)
{
    // kbuf0 0, kbuf1 2304, vbuf0 4608, vbuf1 6912,
    // L2s[0] 9216 (4352), L2s[1] 13568, Rt2s[0] 17920 (6144), Rt2s[1] 24064; tot 30208
    __shared__ __align__(16) unsigned char smx[30208];
    __half* const stage = (__half*)smx;
    __half* kb_[2];  kb_[0] = (__half*)smx;          kb_[1] = (__half*)(smx + 2304);
    __half* vb_[2];  vb_[0] = (__half*)(smx + 4608); vb_[1] = (__half*)(smx + 6912);
    uint32_t* L2s[2];  L2s[0] = (uint32_t*)(smx + 9216);  L2s[1] = (uint32_t*)(smx + 13568);
    uint32_t* Rt2s[2]; Rt2s[0] = (uint32_t*)(smx + 17920); Rt2s[1] = (uint32_t*)(smx + 24064);

    int tid = threadIdx.x;
    int lane = tid & 31, warp = tid >> 5;
    int gid = lane >> 2, tig = lane & 3;
    int wm = warp >> 1, wn = warp & 1;

    int bh = blockIdx.z;
    int b = bh / H_, h = bh % H_;
    int n0 = blockIdx.y * 68;
    int p0 = blockIdx.x * 68;

    const __half* qh_b = qh + (size_t)bh * N_ * HD_;
    const __half* q2_b = q2 + (size_t)bh * N_ * HD_;

    uint32_t aq[4][4];
    for (int i = tid; i < 1024; i += 256) {
        int r = i >> 3, c8 = (i & 7) * 8;
        *(float4*)(stage + r*72 + c8) = *(const float4*)(qh_b + (size_t)(n0+r)*HD_ + c8);
    }
    __syncthreads();
    {
        int rb = warp * 16;
#pragma unroll
        for (int j = 0; j < 4; j++) {
            aq[j][0] = *(const uint32_t*)(stage + (rb+gid)*72   + 16*j + 2*tig);
            aq[j][1] = *(const uint32_t*)(stage + (rb+gid+8)*72 + 16*j + 2*tig);
            aq[j][2] = *(const uint32_t*)(stage + (rb+gid)*72   + 16*j + 2*tig + 8);
            aq[j][3] = *(const uint32_t*)(stage + (rb+gid+8)*72 + 16*j + 2*tig + 8);
        }
    }
    __syncthreads();
    uint32_t aq2[4][4];
    for (int i = tid; i < 1024; i += 256) {
        int r = i >> 3, c8 = (i & 7) * 8;
        *(float4*)(stage + r*72 + c8) = *(const float4*)(q2_b + (size_t)(p0+r)*HD_ + c8);
    }
    __syncthreads();
    {
        int pb = warp * 16;
#pragma unroll
        for (int j = 0; j < 4; j++) {
            aq2[j][0] = *(const uint32_t*)(stage + (pb+gid)*72   + 16*j + 2*tig);
            aq2[j][1] = *(const uint32_t*)(stage + (pb+gid+8)*72 + 16*j + 2*tig);
            aq2[j][2] = *(const uint32_t*)(stage + (pb+gid)*72   + 16*j + 2*tig + 8);
            aq2[j][3] = *(const uint32_t*)(stage + (pb+gid+8)*72 + 16*j + 2*tig + 8);
        }
    }
    __syncthreads();

    float acc[2][8][4];
#pragma unroll
    for (int t = 0; t < 2; t++)
#pragma unroll
        for (int u = 0; u < 8; u++)
#pragma unroll
            for (int e = 0; e < 4; e++) acc[t][u][e] = 0.f;

    uint32_t kB[2], vB[2];
#pragma unroll
    for (int s = 0; s < 2; s++) {
        kB[s] = (uint32_t)__cvta_generic_to_shared(kb_[s]);
        vB[s] = (uint32_t)__cvta_generic_to_shared(vb_[s]);
    }

    int op  = tid >> 7;
    int pr  = (tid & 127) >> 3;
    int pc8 = (tid & 7) * 8;

    // prefetch chunk 0 into parity 0
    {
        const __half* src = (op ? k2 : kh) + (size_t)h * N_ * HD_ + (size_t)pr*HD_ + pc8;
        cp16((op ? vB[0] : kB[0]) + (pr*72 + pc8)*2, src, true);
    }
    asm volatile("cp.async.commit_group;" ::: "memory");

    for (int cid = 0; cid < 130; cid++) {
        int s = cid & 1;
        // prefetch chunk cid+1 into parity s^1
        {
            int nid = cid + 1;
            if (nid < 130) {
                int cc = nid / 13, mm = (nid % 13) * 16 + pr;
                bool ok = mm < N_;
                const __half* basep = (op ? k2 : kh) + (size_t)(cc*H_ + h) * N_ * HD_;
                const __half* src = basep + (ok ? ((size_t)mm*HD_ + pc8) : 0);
                cp16((op ? vB[s^1] : kB[s^1]) + (pr*72 + pc8)*2, src, ok);
            }
        }
        asm volatile("cp.async.commit_group;" ::: "memory");
        asm volatile("cp.async.wait_group 1;" ::: "memory");
        __syncthreads();  // kbuf(cid) visible; L/R(cid-1) published; G3(cid-2) reads of LR[s] retired

        const __half* KT  = kb_[s];
        const __half* K2T = vb_[s];
        float w2c = w2all[b*CH_ + h*NC_ + cid/13];

        // G1
        float lacc[2][4];
#pragma unroll
        for (int t = 0; t < 2; t++)
#pragma unroll
            for (int e = 0; e < 4; e++) lacc[t][e] = 0.f;
#pragma unroll
        for (int j = 0; j < 4; j++) {
            uint32_t b0lo = *(const uint32_t*)(KT + gid*72     + 16*j + 2*tig);
            uint32_t b1lo = *(const uint32_t*)(KT + gid*72     + 16*j + 2*tig + 8);
            uint32_t b0hi = *(const uint32_t*)(KT + (gid+8)*72 + 16*j + 2*tig);
            uint32_t b1hi = *(const uint32_t*)(KT + (gid+8)*72 + 16*j + 2*tig + 8);
            mma16h(lacc[0], aq[j][0],aq[j][1],aq[j][2],aq[j][3], b0lo,b1lo);
            mma16h(lacc[1], aq[j][0],aq[j][1],aq[j][2],aq[j][3], b0hi,b1hi);
        }
        // G2
        float racc[2][4];
#pragma unroll
        for (int t = 0; t < 2; t++)
#pragma unroll
            for (int e = 0; e < 4; e++) racc[t][e] = 0.f;
#pragma unroll
        for (int j = 0; j < 4; j++) {
            uint32_t b0lo = *(const uint32_t*)(K2T + gid*72     + 16*j + 2*tig);
            uint32_t b1lo = *(const uint32_t*)(K2T + gid*72     + 16*j + 2*tig + 8);
            uint32_t b0hi = *(const uint32_t*)(K2T + (gid+8)*72 + 16*j + 2*tig);
            uint32_t b1hi = *(const uint32_t*)(K2T + (gid+8)*72 + 16*j + 2*tig + 8);
            mma16h(racc[0], aq2[j][0],aq2[j][1],aq2[j][2],aq2[j][3], b0lo,b1lo);
            mma16h(racc[1], aq2[j][0],aq2[j][1],aq2[j][2],aq2[j][3], b0hi,b1hi);
        }
        // store L/R(cid) into LR[s]
        {
            int nr = warp*16 + gid;
            int pb = warp*16;
            uint32_t* Ld = L2s[s]; uint32_t* Rd = Rt2s[s];
#pragma unroll
            for (int t = 0; t < 2; t++) {
                float l0 = w2c * fmaxf(0.f, -SCALE_*lacc[t][0]);
                float l1 = w2c * fmaxf(0.f, -SCALE_*lacc[t][1]);
                float l2 = w2c * fmaxf(0.f, -SCALE_*lacc[t][2]);
                float l3 = w2c * fmaxf(0.f, -SCALE_*lacc[t][3]);
                Ld[(4*t+tig)*136 + nr]     = pack_hf2(l0, l1);
                Ld[(4*t+tig)*136 + nr + 8] = pack_hf2(l2, l3);
                float r0 = fmaxf(0.f, SCALE_*racc[t][0]);
                float r1 = fmaxf(0.f, SCALE_*racc[t][1]);
                float r2 = fmaxf(0.f, SCALE_*racc[t][2]);
                float r3 = fmaxf(0.f, SCALE_*racc[t][3]);
                Rd[(pb+gid)*12 + 4*t+tig]   = pack_hf2(r0, r1);
                Rd[(pb+gid+8)*12 + 4*t+tig] = pack_hf2(r2, r3);
            }
        }
        // G3(cid-1) from LR[s^1] (published by this iteration's barrier)
        if (cid > 0) {
            uint32_t* Ls = L2s[s^1]; uint32_t* Rs = Rt2s[s^1];
            uint32_t a[2][4];
#pragma unroll
            for (int t = 0; t < 2; t++) {
                int mb = wm*32 + t*16;
                a[t][0] = Ls[tig*136 + mb+gid];
                a[t][1] = Ls[tig*136 + mb+gid+8];
                a[t][2] = Ls[(tig+4)*136 + mb+gid];
                a[t][3] = Ls[(tig+4)*136 + mb+gid+8];
            }
#pragma unroll
            for (int u = 0; u < 8; u++) {
                int cb = wn*64 + u*8;
                uint32_t b0 = Rs[(cb+gid)*12 + tig];
                uint32_t b1 = Rs[(cb+gid)*12 + tig+4];
                mma16h(acc[0][u], a[0][0],a[0][1],a[0][2],a[0][3], b0,b1);
                mma16h(acc[1][u], a[1][0],a[1][1],a[1][2],a[1][3], b0,b1);
            }
        }
    }
    // epilogue: G3(129) from LR[1]
    __syncthreads();
    {
        uint32_t* Ls = L2s[1]; uint32_t* Rs = Rt2s[1];
        uint32_t a[2][4];
#pragma unroll
        for (int t = 0; t < 2; t++) {
            int mb = wm*32 + t*16;
            a[t][0] = Ls[tig*136 + mb+gid];
            a[t][1] = Ls[tig*136 + mb+gid+8];
            a[t][2] = Ls[(tig+4)*136 + mb+gid];
            a[t][3] = Ls[(tig+4)*136 + mb+gid+8];
        }
#pragma unroll
        for (int u = 0; u < 8; u++) {
            int cb = wn*64 + u*8;
            uint32_t b0 = Rs[(cb+gid)*12 + tig];
            uint32_t b1 = Rs[(cb+gid)*12 + tig+4];
            mma16h(acc[0][u], a[0][0],a[0][1],a[0][2],a[0][3], b0,b1);
            mma16h(acc[1][u], a[1][0],a[1][1],a[1][2],a[1][3], b0,b1);
        }
    }

    __half* o = tmp_out + (size_t)bh * N_ * KP_;
#pragma unroll
    for (int t = 0; t < 2; t++) {
#pragma unroll
        for (int u = 0; u < 8; u++) {
            int n = n0 + wm*32 + t*16 + gid;
            int p = p0 + wn*64 + u*8 + 2*tig;
            *(uint32_t*)(o + (size_t)n*KP_ + p)     = pack_hf2(acc[t][u][0], acc[t][u][1]);
            *(uint32_t*)(o + (size_t)(n+8)*KP_ + p) = pack_hf2(acc[t][u][2], acc[t][u][3]);
        }
    }
}

__global__ void copy_kernel(const float* __restrict__ src, float* __restrict__ dst, int n4)
{
    int i = blockIdx.x * blockDim.x + threadIdx.x;
    if (i < n4) ((float4*)dst)[i] = ((const float4*)src)[i];
}

extern "C" void kernel_launch(void* const* d_in, const int* in_sizes, int n_in,
                              void* d_out, int out_size)
{
    const float* x       = (const float*)d_in[0];
    const float* Wqv     = (const float*)d_in[1];
    const float* Wk      = (const float*)d_in[2];
    const float* Wq_proj = (const float*)d_in[3];
    const float* bq_proj = (const float*)d_in[4];
    const float* Wqk     = (const float*)d_in[5];
    const float* Wqk2    = (const float*)d_in[6];
    const float* Wv      = (const float*)d_in[7];
    const float* Wr_proj = (const float*)d_in[8];
    const float* br_proj = (const float*)d_in[9];
    const float* g1      = (const float*)d_in[10];
    const float* b1      = (const float*)d_in[11];
    const float* g2      = (const float*)d_in[12];
    const float* b2      = (const float*)d_in[13];
    const float* g3      = (const float*)d_in[14];
    const float* b3      = (const float*)d_in[15];
    const float* W1      = (const float*)d_in[16];
    const float* bm1     = (const float*)d_in[17];
    const float* W2      = (const float*)d_in[18];
    const float* bm2     = (const float*)d_in[19];
    float* outp = (float*)d_out;

    float *n1, *qv, *kb, *attn, *ctx, *xx;
    __half *n2, *qq, *akk, *vrT, *tmp, *rectH, *hdn, *h1, *wt;
    cudaGetSymbolAddress((void**)&n1, g_n1);
    cudaGetSymbolAddress((void**)&n2, g_n2);
    cudaGetSymbolAddress((void**)&qv, g_qv);
    cudaGetSymbolAddress((void**)&kb, g_k);
    cudaGetSymbolAddress((void**)&attn, g_attn);
    cudaGetSymbolAddress((void**)&ctx, g_ctx);
    cudaGetSymbolAddress((void**)&qq, g_qq);
    cudaGetSymbolAddress((void**)&akk, g_akk);
    cudaGetSymbolAddress((void**)&vrT, g_vrT);
    cudaGetSymbolAddress((void**)&tmp, g_tmp);
    cudaGetSymbolAddress((void**)&rectH, g_rectH);
    cudaGetSymbolAddress((void**)&xx, g_xx);
    cudaGetSymbolAddress((void**)&hdn, g_hdn);
    cudaGetSymbolAddress((void**)&h1, g_h1);
    cudaGetSymbolAddress((void**)&wt, g_wt);

    __half* n2x = n2;
    __half* n2a = n2 + (size_t)B_*N_*C_;
    const long zQ = (long)BH_*N_*HD_;
    const long zK = (long)CH_*N_*HD_;
    __half* qh = qq;
    __half* q2 = qq + zQ;
    __half* kh = akk;
    __half* k2 = akk + zK;

    // 0) weight transpose-convert; zero K-pads
    transpose_all<<<1728, dim3(32, 8)>>>(Wqk, Wqk2, Wv, Wr_proj, W1, W2, wt);
    zero_pads<<<BH_*N_ + BH_*HD_, 32>>>(tmp, vrT);

    // 1) LayerNorms
    ln_kernel<<<26, 128>>>(x, n1, g1, b1, 26, 26, 0, (long)T_*C_, 0);
    ln_kernel<<<26*N_, 128>>>(x + C_, n2, g2, b2, 26*N_, N_, (long)T_*C_, C_, 1);

    // 2) cls path
    rowgemm_cls<<<dim3(26, 12), 256>>>(n1, Wqv, Wk, qv, kb);
    attn_cls_kernel<<<B_, 384>>>(qv, kb, attn, ctx);
    rowgemm<<<dim3(B_, 6), 256>>>(ctx, Wq_proj, bq_proj, xx, C_, (long)T_*C_);

    // 3) head projections
    gemm_h<<<dim3(6, 25, 2), 256>>>(n2x, wt + OW_QK, nullptr, nullptr, nullptr, qq,
                                    B_*N_, C_, C_, C_, C_, 0, 1, 0, 147456, zQ);
    gemm_h64<<<dim3(6, 31, 2), 256>>>(n2a, wt + OW_QK, nullptr, nullptr, nullptr, akk,
                                      NC_*N_, C_, C_, C_, C_, 0, 1, 0, 147456, zK);
    gemm_h64<<<dim3(6, 49), 256>>>(n2x, wt + OW_V, nullptr, nullptr, nullptr, vrT,
                                   B_*N_, C_, C_, C_, C_, 0, 4, 0, 0, 0);

    // 4) fused rectified attention core -> tmp (single-sync skewed pipeline)
    dim3 gf(2, 2, BH_);
    fused_attn5<<<gf, 256>>>(qh, kh, q2, k2, attn, tmp);

    // 5) rect = tmp @ vr -> rectH flat [bh][n][d]
    gemm_h64<<<dim3(1, 4, BH_), 256>>>(tmp, vrT, nullptr, nullptr, nullptr, rectH,
                                       N_, HD_, KP_, KP_, KP_, 0, 5,
                                       (long)N_*KP_, (long)HD_*KP_, 0);

    // 6) rect projection + residual -> xx rows 1..196
    gemm_h64<<<dim3(6, 49), 256>>>(rectH, wt + OW_R, br_proj, x, xx, nullptr,
                                   B_*N_, C_, C_, C_, C_, 0, 2, 0, 0, 0);

    // 7) MLP
    ln_kernel<<<B_*T_, 128>>>(xx, hdn, g3, b3, B_*T_, B_*T_, 0, C_, 1);
    gemm_h<<<dim3(24, 25), 256>>>(hdn, wt + OW_1, bm1, nullptr, nullptr, h1,
                                  B_*T_, 4*C_, C_, C_, C_, 1, 0, 0, 0, 0);
    gemm_h64<<<dim3(6, 50), 256>>>(h1, wt + OW_2, bm2, xx, outp, nullptr,
                                   B_*T_, C_, 4*C_, 4*C_, 4*C_, 0, 0, 0, 0, 0);

    // 8) anchors pass-through
    int n4 = NC_*T_*C_/4;
    copy_kernel<<<(n4 + 255)/256, 256>>>(x + (long)16*T_*C_, outp + (long)16*T_*C_, n4);
}

// round 17
// speedup vs baseline: 1.2176x; 1.2176x over previous
#include <cuda_runtime.h>
#include <cuda_fp16.h>
#include <cstdint>

#define B_  16
#define NC_ 10
#define H_  6
#define C_  384
#define HD_ 64
#define T_  197
#define N_  196
#define BH_ (B_*H_)
#define CH_ (NC_*H_)
#define SCALE_ 0.125f
#define KP_ 224

#define OW_QK  0
#define OW_QK2 147456
#define OW_V   294912
#define OW_R   442368
#define OW_1   589824
#define OW_2   1179648
#define WT_TOT 1769472
#define TRN_BLKS 1728
#define PAD_BLKS (BH_*N_ + BH_*HD_)   // 18816... wait: BH_*N_=18816? 96*196=18816; +96*64=6144 -> 24960

__device__ float g_n1 [26*C_];
__device__ __align__(16) __half g_n2[26*N_*C_];
__device__ float g_qv [NC_*2*C_];
__device__ float g_k  [B_*C_];
__device__ float g_attn[B_*CH_];
__device__ float g_ctx[B_*C_];
__device__ __align__(16) __half g_qq [2*BH_*N_*HD_];   // qh | q2
__device__ __align__(16) __half g_akk[2*CH_*N_*HD_];   // kh | k2
__device__ __align__(16) __half g_vrT[BH_*HD_*KP_];
__device__ __align__(16) __half g_tmp[BH_*N_*KP_];
__device__ __align__(16) __half g_rectH[B_*N_*C_];
__device__ float g_xx [B_*T_*C_];
__device__ __align__(16) __half g_hdn[B_*T_*C_];
__device__ __align__(16) __half g_h1 [B_*T_*4*C_];
__device__ __align__(16) __half g_wt [WT_TOT];

#define U32(x) __float_as_uint(x)

__device__ __forceinline__ void mma16h(float* c, uint32_t a0, uint32_t a1, uint32_t a2, uint32_t a3,
                                       uint32_t b0, uint32_t b1)
{
    asm volatile("mma.sync.aligned.m16n8k16.row.col.f32.f16.f16.f32 "
                 "{%0,%1,%2,%3},{%4,%5,%6,%7},{%8,%9},{%0,%1,%2,%3};\n"
                 : "+f"(c[0]), "+f"(c[1]), "+f"(c[2]), "+f"(c[3])
                 : "r"(a0), "r"(a1), "r"(a2), "r"(a3), "r"(b0), "r"(b1));
}

__device__ __forceinline__ uint32_t pack_hf2(float lo, float hi) {
    uint32_t d;
    asm("cvt.rn.f16x2.f32 %0, %1, %2;" : "=r"(d) : "f"(hi), "f"(lo));
    return d;
}

__device__ __forceinline__ void cp16(uint32_t dst, const void* src, bool p) {
    int sz = p ? 16 : 0;
    asm volatile("cp.async.cg.shared.global [%0], [%1], 16, %2;" :: "r"(dst), "l"(src), "r"(sz));
}

__device__ __forceinline__ float gelu_f(float x) {
    return 0.5f * x * (1.f + erff(x * 0.7071067811865475f));
}

__device__ __forceinline__ size_t omap(int mode, int r, int c, int N, int bz)
{
    if (mode == 0) return (size_t)r * N + c;
    if (mode == 1) {
        int bq = r / N_, n = r % N_;
        return ((size_t)(bq*H_ + (c >> 6)) * N_ + n) * HD_ + (c & 63);
    }
    if (mode == 2) {
        int bq = r / N_, n = r % N_;
        return ((size_t)bq*T_ + 1 + n) * C_ + c;
    }
    if (mode == 4) {
        int bq = r / N_, n = r % N_;
        return ((size_t)(bq*H_ + (c >> 6)) * HD_ + (c & 63)) * KP_ + n;
    }
    return ((size_t)bz * N_ + r) * HD_ + c; // 5
}

// ---------------- merged weight transpose-convert + pad zeroing (one launch) -----
__global__ void transpose_all(const float* __restrict__ Wqk, const float* __restrict__ Wqk2,
                              const float* __restrict__ Wv,  const float* __restrict__ Wr,
                              const float* __restrict__ W1,  const float* __restrict__ W2,
                              __half* __restrict__ wt,
                              __half* __restrict__ tmp, __half* __restrict__ vrT)
{
    int bid = blockIdx.x;
    if (bid >= TRN_BLKS) {
        // pad-zero duty: blocks TRN_BLKS .. TRN_BLKS + ceil(24960/8)-1, each handles 8 rows
        int base = (bid - TRN_BLKS) * 8 + (threadIdx.y);   // 8 rows per block via ty
        int row = base;
        int t = threadIdx.x;
        if (t < KP_ - N_) {
            // rows [0, BH_*N_) -> tmp ; rows [BH_*N_, BH_*N_+BH_*HD_) -> vrT
            if (row < BH_*N_) tmp[(size_t)row*KP_ + N_ + t] = __float2half(0.f);
            else if (row < BH_*N_ + BH_*HD_) {
                int r2 = row - BH_*N_;
                vrT[(size_t)r2*KP_ + N_ + t] = __float2half(0.f);
            }
        }
        return;
    }
    __shared__ float tile[32][33];
    const float* src; __half* dst; int K, N, tn;
    if      (bid < 144)  { src = Wqk;  dst = wt + OW_QK;  K = C_;   N = C_;   tn = bid; }
    else if (bid < 288)  { src = Wqk2; dst = wt + OW_QK2; K = C_;   N = C_;   tn = bid - 144; }
    else if (bid < 432)  { src = Wv;   dst = wt + OW_V;   K = C_;   N = C_;   tn = bid - 288; }
    else if (bid < 576)  { src = Wr;   dst = wt + OW_R;   K = C_;   N = C_;   tn = bid - 432; }
    else if (bid < 1152) { src = W1;   dst = wt + OW_1;   K = C_;   N = 4*C_; tn = bid - 576; }
    else                 { src = W2;   dst = wt + OW_2;   K = 4*C_; N = C_;   tn = bid - 1152; }
    int ntx = N >> 5;
    int nb = (tn % ntx) * 32, kb = (tn / ntx) * 32;
    int tx = threadIdx.x, ty = threadIdx.y;
#pragma unroll
    for (int i = 0; i < 32; i += 8)
        tile[ty + i][tx] = src[(size_t)(kb + ty + i) * N + nb + tx];
    __syncthreads();
#pragma unroll
    for (int i = 0; i < 32; i += 8)
        dst[(size_t)(nb + ty + i) * K + kb + tx] = __float2half(tile[tx][ty + i]);
}

// ---------------- LayerNorm ----------------
__global__ void ln_kernel(const float* __restrict__ in, void* __restrict__ outv,
                          const float* __restrict__ g, const float* __restrict__ bt,
                          int rows, int inner, long outer_stride, long inner_stride, int h16)
{
    int row = blockIdx.x;
    if (row >= rows) return;
    const float* src = in + (long)(row / inner) * outer_stride + (long)(row % inner) * inner_stride;
    int t = threadIdx.x;
    float v[3]; float s = 0.f;
#pragma unroll
    for (int i = 0; i < 3; i++) { v[i] = src[t + i*128]; s += v[i]; }
    __shared__ float red[4];
#pragma unroll
    for (int o = 16; o > 0; o >>= 1) s += __shfl_xor_sync(0xffffffffu, s, o);
    if ((t & 31) == 0) red[t >> 5] = s;
    __syncthreads();
    float mean = (red[0] + red[1] + red[2] + red[3]) * (1.f/384.f);
    float q = 0.f;
#pragma unroll
    for (int i = 0; i < 3; i++) { float d = v[i] - mean; q += d*d; }
#pragma unroll
    for (int o = 16; o > 0; o >>= 1) q += __shfl_xor_sync(0xffffffffu, q, o);
    __syncthreads();
    if ((t & 31) == 0) red[t >> 5] = q;
    __syncthreads();
    float var = (red[0] + red[1] + red[2] + red[3]) * (1.f/384.f);
    float rs = rsqrtf(var + 1e-5f);
#pragma unroll
    for (int i = 0; i < 3; i++) {
        int c = t + i*128;
        float o = (v[i] - mean) * rs * g[c] + bt[c];
        if (h16) ((__half*)outv)[(long)row*C_ + c] = __float2half(o);
        else     ((float*)outv)[(long)row*C_ + c] = o;
    }
}

// ---------------- merged cls qv/k row GEMM ----------------
__global__ __launch_bounds__(256)
void rowgemm_cls(const float* __restrict__ n1, const float* __restrict__ Wqv,
                 const float* __restrict__ Wk, float* __restrict__ qv, float* __restrict__ kb)
{
    __shared__ float a_s[384];
    __shared__ float part[256];
    int bx = blockIdx.x, by = blockIdx.y;
    const float* A; const float* W; float* out; int N;
    if (bx < NC_) { A = n1 + (16+bx)*C_; W = Wqv; out = qv + bx*2*C_; N = 2*C_; }
    else {
        if (by >= 6) return;
        A = n1 + (bx-NC_)*C_; W = Wk; out = kb + (bx-NC_)*C_; N = C_;
    }
    int cb = by * 64;
    int t = threadIdx.x;
    for (int i = t; i < 384; i += 256) a_s[i] = A[i];
    __syncthreads();
    int col = t & 63, sp = t >> 6;
    int base = sp * 96;
    float s0 = 0.f, s1 = 0.f;
    const float* Wp = W + (size_t)base*N + cb + col;
#pragma unroll 8
    for (int k = 0; k < 96; k += 2) {
        s0 += a_s[base+k]   * Wp[(size_t)(k)*N];
        s1 += a_s[base+k+1] * Wp[(size_t)(k+1)*N];
    }
    part[t] = s0 + s1;
    __syncthreads();
    if (t < 64) out[cb + t] = part[t] + part[64+t] + part[128+t] + part[192+t];
}

__global__ __launch_bounds__(256)
void rowgemm(const float* __restrict__ A, const float* __restrict__ W,
             const float* __restrict__ bias, float* __restrict__ out,
             int N, long out_stride)
{
    __shared__ float a_s[384];
    __shared__ float part[256];
    int row = blockIdx.x, cb = blockIdx.y * 64;
    int t = threadIdx.x;
    for (int i = t; i < 384; i += 256) a_s[i] = A[(size_t)row*384 + i];
    __syncthreads();
    int col = t & 63, sp = t >> 6;
    int base = sp * 96;
    float s0 = 0.f, s1 = 0.f;
    const float* Wp = W + (size_t)base*N + cb + col;
#pragma unroll 8
    for (int k = 0; k < 96; k += 2) {
        s0 += a_s[base+k]   * Wp[(size_t)(k)*N];
        s1 += a_s[base+k+1] * Wp[(size_t)(k+1)*N];
    }
    part[t] = s0 + s1;
    __syncthreads();
    if (t < 64) {
        float v = part[t] + part[64+t] + part[128+t] + part[192+t];
        if (bias) v += bias[cb + t];
        out[(size_t)row*out_stride + cb + t] = v;
    }
}

// ---------------- cls attention ----------------
__global__ void attn_cls_kernel(const float* __restrict__ qv, const float* __restrict__ k,
                                float* __restrict__ attn, float* __restrict__ ctx)
{
    int b = blockIdx.x, t = threadIdx.x;
    __shared__ float sl[CH_];
    if (t < CH_) {
        int n = t / H_, h = t % H_;
        float s = 0.f;
        for (int d = 0; d < HD_; d++) s += qv[n*2*C_ + h*HD_ + d] * k[b*C_ + h*HD_ + d];
        sl[t] = s * SCALE_;
    }
    __syncthreads();
    if (t < H_) {
        float mx = -1e30f;
        for (int n = 0; n < NC_; n++) mx = fmaxf(mx, sl[n*H_ + t]);
        float sum = 0.f;
        for (int n = 0; n < NC_; n++) { float e = expf(sl[n*H_ + t] - mx); sl[n*H_ + t] = e; sum += e; }
        float inv = 1.f / sum;
        for (int n = 0; n < NC_; n++) { sl[n*H_ + t] *= inv; attn[b*CH_ + n*H_ + t] = sl[n*H_ + t]; }
    }
    __syncthreads();
    {
        int h = t >> 6, d = t & 63;
        float s = 0.f;
        for (int n = 0; n < NC_; n++) s += sl[n*H_ + h] * qv[n*2*C_ + C_ + h*HD_ + d];
        ctx[b*C_ + t] = s;
    }
}

// ---------------- all-fp16 GEMM, 128-row M tile ----------------
__global__ __launch_bounds__(256, 2)
void gemm_h(const __half* __restrict__ A, const __half* __restrict__ Bt,
            const float* __restrict__ bias, const float* __restrict__ res,
            float* __restrict__ outF, __half* __restrict__ outH,
            int M, int N, int K, int lda, int ldb, int act, int mode,
            long zA, long zB, long zO)
{
    __shared__ __align__(16) __half As[2][128*40];
    __shared__ __align__(16) __half Bs[2][64*40];
    A  += (size_t)blockIdx.z * zA;
    Bt += (size_t)blockIdx.z * zB;
    if (outH) outH += (size_t)blockIdx.z * zO;
    else if (outF) outF += (size_t)blockIdx.z * zO;

    int tid = threadIdx.x;
    int lane = tid & 31, warp = tid >> 5;
    int gid = lane >> 2, tig = lane & 3;
    int wm = warp >> 1, wn = warp & 1;
    int m0 = blockIdx.y * 128, n0 = blockIdx.x * 64;

    int ar = tid >> 1, ac = (tid & 1) * 16;
    int br = tid >> 2, bc = (tid & 3) * 8;

    uint32_t aB[2], bB[2];
#pragma unroll
    for (int s = 0; s < 2; s++) {
        aB[s] = (uint32_t)__cvta_generic_to_shared(&As[s][0]);
        bB[s] = (uint32_t)__cvta_generic_to_shared(&Bs[s][0]);
    }

    bool okA = (m0 + ar < M);
    int nk = K >> 5;

#define GISSUE(it_, st_) do { \
    int kk = (it_) * 32; \
    const __half* sa = A + (size_t)(m0 + ar) * lda + kk + ac; \
    cp16(aB[st_] + (ar*40 + ac)*2,      okA ? sa : (const __half*)A,       okA); \
    cp16(aB[st_] + (ar*40 + ac)*2 + 16, okA ? (sa + 8) : (const __half*)A, okA); \
    cp16(bB[st_] + (br*40 + bc)*2, Bt + (size_t)(n0 + br) * ldb + kk + bc, true); \
    asm volatile("cp.async.commit_group;" ::: "memory"); \
} while (0)

    float acc[2][4][4];
#pragma unroll
    for (int t = 0; t < 2; t++)
#pragma unroll
        for (int u = 0; u < 4; u++)
#pragma unroll
            for (int e = 0; e < 4; e++) acc[t][u][e] = 0.f;

    GISSUE(0, 0);

    for (int it = 0; it < nk; it++) {
        asm volatile("cp.async.wait_group 0;" ::: "memory");
        __syncthreads();
        int st = it & 1;
        if (it + 1 < nk) GISSUE(it + 1, st ^ 1);
        const __half* Af = As[st];
        const __half* Bf = Bs[st];
#pragma unroll
        for (int ks = 0; ks < 2; ks++) {
            int ko = ks * 16;
            uint32_t a[2][4];
#pragma unroll
            for (int t = 0; t < 2; t++) {
                int mb = wm*32 + t*16;
                a[t][0] = *(const uint32_t*)(Af + (mb+gid)*40   + ko + 2*tig);
                a[t][1] = *(const uint32_t*)(Af + (mb+gid+8)*40 + ko + 2*tig);
                a[t][2] = *(const uint32_t*)(Af + (mb+gid)*40   + ko + 2*tig + 8);
                a[t][3] = *(const uint32_t*)(Af + (mb+gid+8)*40 + ko + 2*tig + 8);
            }
#pragma unroll
            for (int u = 0; u < 4; u++) {
                int cb = wn*32 + u*8;
                uint32_t b0 = *(const uint32_t*)(Bf + (cb+gid)*40 + ko + 2*tig);
                uint32_t b1 = *(const uint32_t*)(Bf + (cb+gid)*40 + ko + 2*tig + 8);
                mma16h(acc[0][u], a[0][0],a[0][1],a[0][2],a[0][3], b0,b1);
                mma16h(acc[1][u], a[1][0],a[1][1],a[1][2],a[1][3], b0,b1);
            }
        }
    }
#undef GISSUE

    int bz = blockIdx.z;
#pragma unroll
    for (int t = 0; t < 2; t++) {
#pragma unroll
        for (int u = 0; u < 4; u++) {
            int rb = m0 + wm*32 + t*16 + gid;
            int cb = n0 + wn*32 + u*8 + 2*tig;
#pragma unroll
            for (int e = 0; e < 4; e++) {
                int r = rb + (e >> 1) * 8;
                int c = cb + (e & 1);
                if (r >= M) continue;
                float v = acc[t][u][e];
                if (bias) v += bias[c];
                if (act) v = gelu_f(v);
                size_t idx = omap(mode, r, c, N, bz);
                if (outH) outH[idx] = __float2half(v);
                else {
                    if (res) v += res[idx];
                    outF[idx] = v;
                }
            }
        }
    }
}

// ---------------- all-fp16 GEMM, 64-row M tile (2x4 warps, occ 3) ----------------
__global__ __launch_bounds__(256, 3)
void gemm_h64(const __half* __restrict__ A, const __half* __restrict__ Bt,
              const float* __restrict__ bias, const float* __restrict__ res,
              float* __restrict__ outF, __half* __restrict__ outH,
              int M, int N, int K, int lda, int ldb, int act, int mode,
              long zA, long zB, long zO)
{
    __shared__ __align__(16) __half As[2][64*40];
    __shared__ __align__(16) __half Bs[2][64*40];
    A  += (size_t)blockIdx.z * zA;
    Bt += (size_t)blockIdx.z * zB;
    if (outH) outH += (size_t)blockIdx.z * zO;
    else if (outF) outF += (size_t)blockIdx.z * zO;

    int tid = threadIdx.x;
    int lane = tid & 31, warp = tid >> 5;
    int gid = lane >> 2, tig = lane & 3;
    int wm = warp >> 2, wn = warp & 3;
    int m0 = blockIdx.y * 64, n0 = blockIdx.x * 64;

    int ar = tid >> 2, ac = (tid & 3) * 8;
    int br = tid >> 2, bc = (tid & 3) * 8;

    uint32_t aB[2], bB[2];
#pragma unroll
    for (int s = 0; s < 2; s++) {
        aB[s] = (uint32_t)__cvta_generic_to_shared(&As[s][0]);
        bB[s] = (uint32_t)__cvta_generic_to_shared(&Bs[s][0]);
    }

    bool okA = (m0 + ar < M);
    int nk = K >> 5;

#define GISSUE64(it_, st_) do { \
    int kk = (it_) * 32; \
    const __half* sa = A + (size_t)(m0 + ar) * lda + kk + ac; \
    cp16(aB[st_] + (ar*40 + ac)*2, okA ? sa : (const __half*)A, okA); \
    cp16(bB[st_] + (br*40 + bc)*2, Bt + (size_t)(n0 + br) * ldb + kk + bc, true); \
    asm volatile("cp.async.commit_group;" ::: "memory"); \
} while (0)

    float acc[2][2][4];
#pragma unroll
    for (int t = 0; t < 2; t++)
#pragma unroll
        for (int u = 0; u < 2; u++)
#pragma unroll
            for (int e = 0; e < 4; e++) acc[t][u][e] = 0.f;

    GISSUE64(0, 0);

    for (int it = 0; it < nk; it++) {
        asm volatile("cp.async.wait_group 0;" ::: "memory");
        __syncthreads();
        int st = it & 1;
        if (it + 1 < nk) GISSUE64(it + 1, st ^ 1);
        const __half* Af = As[st];
        const __half* Bf = Bs[st];
#pragma unroll
        for (int ks = 0; ks < 2; ks++) {
            int ko = ks * 16;
            uint32_t a[2][4];
#pragma unroll
            for (int t = 0; t < 2; t++) {
                int mb = wm*32 + t*16;
                a[t][0] = *(const uint32_t*)(Af + (mb+gid)*40   + ko + 2*tig);
                a[t][1] = *(const uint32_t*)(Af + (mb+gid+8)*40 + ko + 2*tig);
                a[t][2] = *(const uint32_t*)(Af + (mb+gid)*40   + ko + 2*tig + 8);
                a[t][3] = *(const uint32_t*)(Af + (mb+gid+8)*40 + ko + 2*tig + 8);
            }
#pragma unroll
            for (int u = 0; u < 2; u++) {
                int cb = wn*16 + u*8;
                uint32_t b0 = *(const uint32_t*)(Bf + (cb+gid)*40 + ko + 2*tig);
                uint32_t b1 = *(const uint32_t*)(Bf + (cb+gid)*40 + ko + 2*tig + 8);
                mma16h(acc[0][u], a[0][0],a[0][1],a[0][2],a[0][3], b0,b1);
                mma16h(acc[1][u], a[1][0],a[1][1],a[1][2],a[1][3], b0,b1);
            }
        }
    }
#undef GISSUE64

    int bz = blockIdx.z;
#pragma unroll
    for (int t = 0; t < 2; t++) {
#pragma unroll
        for (int u = 0; u < 2; u++) {
            int rb = m0 + wm*32 + t*16 + gid;
            int cb = n0 + wn*16 + u*8 + 2*tig;
#pragma unroll
            for (int e = 0; e < 4; e++) {
                int r = rb + (e >> 1) * 8;
                int c = cb + (e & 1);
                if (r >= M) continue;
                float v = acc[t][u][e];
                if (bias) v += bias[c];
                if (act) v = gelu_f(v);
                size_t idx = omap(mode, r, c, N, bz);
                if (outH) outH[idx] = __float2half(v);
                else {
                    if (res) v += res[idx];
                    outF[idx] = v;
                }
            }
        }
    }
}

// ---------------- fused rectified attention core (R12 proven version) ----------------
__global__ __launch_bounds__(256, 2)
void fused_attn3(const __half* __restrict__ qh, const __half* __restrict__ kh,
                 const __half* __restrict__ q2, const __half* __restrict__ k2,
                 const float* __restrict__ w2all, __half* __restrict__ tmp_out)
{
    __shared__ __align__(16) unsigned char smx[19712];
    __half* const stage = (__half*)smx;
    __half* const kbuf0 = (__half*)smx;
    __half* const kbuf1 = kbuf0 + 16*72;
    __half* const vbuf0 = kbuf1 + 16*72;
    __half* const vbuf1 = vbuf0 + 16*72;
    uint32_t* const L2_s  = (uint32_t*)(smx + 9216);
    uint32_t* const Rt2_s = (uint32_t*)(smx + 13568);

    int tid = threadIdx.x;
    int lane = tid & 31, warp = tid >> 5;
    int gid = lane >> 2, tig = lane & 3;
    int wm = warp >> 1, wn = warp & 1;

    int bh = blockIdx.z;
    int b = bh / H_, h = bh % H_;
    int n0 = blockIdx.y * 68;
    int p0 = blockIdx.x * 68;

    const __half* qh_b = qh + (size_t)bh * N_ * HD_;
    const __half* q2_b = q2 + (size_t)bh * N_ * HD_;

    uint32_t aq[4][4];
    for (int i = tid; i < 1024; i += 256) {
        int r = i >> 3, c8 = (i & 7) * 8;
        *(float4*)(stage + r*72 + c8) = *(const float4*)(qh_b + (size_t)(n0+r)*HD_ + c8);
    }
    __syncthreads();
    {
        int rb = warp * 16;
#pragma unroll
        for (int j = 0; j < 4; j++) {
            aq[j][0] = *(const uint32_t*)(stage + (rb+gid)*72   + 16*j + 2*tig);
            aq[j][1] = *(const uint32_t*)(stage + (rb+gid+8)*72 + 16*j + 2*tig);
            aq[j][2] = *(const uint32_t*)(stage + (rb+gid)*72   + 16*j + 2*tig + 8);
            aq[j][3] = *(const uint32_t*)(stage + (rb+gid+8)*72 + 16*j + 2*tig + 8);
        }
    }
    __syncthreads();
    uint32_t aq2[4][4];
    for (int i = tid; i < 1024; i += 256) {
        int r = i >> 3, c8 = (i & 7) * 8;
        *(float4*)(stage + r*72 + c8) = *(const float4*)(q2_b + (size_t)(p0+r)*HD_ + c8);
    }
    __syncthreads();
    {
        int pb = warp * 16;
#pragma unroll
        for (int j = 0; j < 4; j++) {
            aq2[j][0] = *(const uint32_t*)(stage + (pb+gid)*72   + 16*j + 2*tig);
            aq2[j][1] = *(const uint32_t*)(stage + (pb+gid+8)*72 + 16*j + 2*tig);
            aq2[j][2] = *(const uint32_t*)(stage + (pb+gid)*72   + 16*j + 2*tig + 8);
            aq2[j][3] = *(const uint32_t*)(stage + (pb+gid+8)*72 + 16*j + 2*tig + 8);
        }
    }
    __syncthreads();

    float acc[2][8][4];
#pragma unroll
    for (int t = 0; t < 2; t++)
#pragma unroll
        for (int u = 0; u < 8; u++)
#pragma unroll
            for (int e = 0; e < 4; e++) acc[t][u][e] = 0.f;

    uint32_t kd0 = (uint32_t)__cvta_generic_to_shared(kbuf0);
    uint32_t kd1 = (uint32_t)__cvta_generic_to_shared(kbuf1);
    uint32_t vd0 = (uint32_t)__cvta_generic_to_shared(vbuf0);
    uint32_t vd1 = (uint32_t)__cvta_generic_to_shared(vbuf1);

    int op  = tid >> 7;
    int pr  = (tid & 127) >> 3;
    int pc8 = (tid & 7) * 8;

    {
        const __half* src = (op ? k2 : kh) + (size_t)h * N_ * HD_ + (size_t)pr*HD_ + pc8;
        uint32_t d = (op ? vd0 : kd0) + (pr*72 + pc8)*2;
        cp16(d, src, true);
    }
    asm volatile("cp.async.commit_group;" ::: "memory");

    int buf = 0;
    for (int c = 0; c < NC_; c++) {
        float w2c = w2all[b*CH_ + h*NC_ + c];
        for (int mc = 0; mc < 13; mc++) {
            {
                int nc2 = c, nm = mc + 1;
                if (nm == 13) { nm = 0; nc2 = c + 1; }
                if (nc2 < NC_) {
                    int m = nm*16 + pr;
                    bool ok = m < N_;
                    const __half* basep = (op ? k2 : kh) + (size_t)(nc2*H_ + h) * N_ * HD_;
                    const __half* src = basep + (ok ? ((size_t)m*HD_ + pc8) : 0);
                    uint32_t d = (op ? (buf ? vd0 : vd1) : (buf ? kd0 : kd1)) + (pr*72 + pc8)*2;
                    cp16(d, src, ok);
                }
            }
            asm volatile("cp.async.commit_group;" ::: "memory");
            asm volatile("cp.async.wait_group 1;" ::: "memory");
            __syncthreads();

            const __half* KT  = buf ? kbuf1 : kbuf0;
            const __half* K2T = buf ? vbuf1 : vbuf0;

            float lacc[2][4];
#pragma unroll
            for (int t = 0; t < 2; t++)
#pragma unroll
                for (int e = 0; e < 4; e++) lacc[t][e] = 0.f;
#pragma unroll
            for (int j = 0; j < 4; j++) {
                uint32_t b0lo = *(const uint32_t*)(KT + gid*72     + 16*j + 2*tig);
                uint32_t b1lo = *(const uint32_t*)(KT + gid*72     + 16*j + 2*tig + 8);
                uint32_t b0hi = *(const uint32_t*)(KT + (gid+8)*72 + 16*j + 2*tig);
                uint32_t b1hi = *(const uint32_t*)(KT + (gid+8)*72 + 16*j + 2*tig + 8);
                mma16h(lacc[0], aq[j][0],aq[j][1],aq[j][2],aq[j][3], b0lo,b1lo);
                mma16h(lacc[1], aq[j][0],aq[j][1],aq[j][2],aq[j][3], b0hi,b1hi);
            }
            float racc[2][4];
#pragma unroll
            for (int t = 0; t < 2; t++)
#pragma unroll
                for (int e = 0; e < 4; e++) racc[t][e] = 0.f;
#pragma unroll
            for (int j = 0; j < 4; j++) {
                uint32_t b0lo = *(const uint32_t*)(K2T + gid*72     + 16*j + 2*tig);
                uint32_t b1lo = *(const uint32_t*)(K2T + gid*72     + 16*j + 2*tig + 8);
                uint32_t b0hi = *(const uint32_t*)(K2T + (gid+8)*72 + 16*j + 2*tig);
                uint32_t b1hi = *(const uint32_t*)(K2T + (gid+8)*72 + 16*j + 2*tig + 8);
                mma16h(racc[0], aq2[j][0],aq2[j][1],aq2[j][2],aq2[j][3], b0lo,b1lo);
                mma16h(racc[1], aq2[j][0],aq2[j][1],aq2[j][2],aq2[j][3], b0hi,b1hi);
            }
            {
                int nr = warp*16 + gid;
                int pb = warp*16;
#pragma unroll
                for (int t = 0; t < 2; t++) {
                    float l0 = w2c * fmaxf(0.f, -SCALE_*lacc[t][0]);
                    float l1 = w2c * fmaxf(0.f, -SCALE_*lacc[t][1]);
                    float l2 = w2c * fmaxf(0.f, -SCALE_*lacc[t][2]);
                    float l3 = w2c * fmaxf(0.f, -SCALE_*lacc[t][3]);
                    L2_s[(4*t+tig)*136 + nr]     = pack_hf2(l0, l1);
                    L2_s[(4*t+tig)*136 + nr + 8] = pack_hf2(l2, l3);
                    float r0 = fmaxf(0.f, SCALE_*racc[t][0]);
                    float r1 = fmaxf(0.f, SCALE_*racc[t][1]);
                    float r2 = fmaxf(0.f, SCALE_*racc[t][2]);
                    float r3 = fmaxf(0.f, SCALE_*racc[t][3]);
                    Rt2_s[(pb+gid)*12 + 4*t+tig]   = pack_hf2(r0, r1);
                    Rt2_s[(pb+gid+8)*12 + 4*t+tig] = pack_hf2(r2, r3);
                }
            }
            __syncthreads();
            {
                uint32_t a[2][4];
#pragma unroll
                for (int t = 0; t < 2; t++) {
                    int mb = wm*32 + t*16;
                    a[t][0] = L2_s[tig*136 + mb+gid];
                    a[t][1] = L2_s[tig*136 + mb+gid+8];
                    a[t][2] = L2_s[(tig+4)*136 + mb+gid];
                    a[t][3] = L2_s[(tig+4)*136 + mb+gid+8];
                }
#pragma unroll
                for (int u = 0; u < 8; u++) {
                    int cb = wn*64 + u*8;
                    uint32_t b0 = Rt2_s[(cb+gid)*12 + tig];
                    uint32_t b1 = Rt2_s[(cb+gid)*12 + tig+4];
                    mma16h(acc[0][u], a[0][0],a[0][1],a[0][2],a[0][3], b0,b1);
                    mma16h(acc[1][u], a[1][0],a[1][1],a[1][2],a[1][3], b0,b1);
                }
            }
            buf ^= 1;
        }
    }

    __half* o = tmp_out + (size_t)bh * N_ * KP_;
#pragma unroll
    for (int t = 0; t < 2; t++) {
#pragma unroll
        for (int u = 0; u < 8; u++) {
            int n = n0 + wm*32 + t*16 + gid;
            int p = p0 + wn*64 + u*8 + 2*tig;
            *(uint32_t*)(o + (size_t)n*KP_ + p)     = pack_hf2(acc[t][u][0], acc[t][u][1]);
            *(uint32_t*)(o + (size_t)(n+8)*KP_ + p) = pack_hf2(acc[t][u][2], acc[t][u][3]);
        }
    }
}

__global__ void copy_kernel(const float* __restrict__ src, float* __restrict__ dst, int n4)
{
    int i = blockIdx.x * blockDim.x + threadIdx.x;
    if (i < n4) ((float4*)dst)[i] = ((const float4*)src)[i];
}

extern "C" void kernel_launch(void* const* d_in, const int* in_sizes, int n_in,
                              void* d_out, int out_size)
{
    const float* x       = (const float*)d_in[0];
    const float* Wqv     = (const float*)d_in[1];
    const float* Wk      = (const float*)d_in[2];
    const float* Wq_proj = (const float*)d_in[3];
    const float* bq_proj = (const float*)d_in[4];
    const float* Wqk     = (const float*)d_in[5];
    const float* Wqk2    = (const float*)d_in[6];
    const float* Wv      = (const float*)d_in[7];
    const float* Wr_proj = (const float*)d_in[8];
    const float* br_proj = (const float*)d_in[9];
    const float* g1      = (const float*)d_in[10];
    const float* b1      = (const float*)d_in[11];
    const float* g2      = (const float*)d_in[12];
    const float* b2      = (const float*)d_in[13];
    const float* g3      = (const float*)d_in[14];
    const float* b3      = (const float*)d_in[15];
    const float* W1      = (const float*)d_in[16];
    const float* bm1     = (const float*)d_in[17];
    const float* W2      = (const float*)d_in[18];
    const float* bm2     = (const float*)d_in[19];
    float* outp = (float*)d_out;

    float *n1, *qv, *kb, *attn, *ctx, *xx;
    __half *n2, *qq, *akk, *vrT, *tmp, *rectH, *hdn, *h1, *wt;
    cudaGetSymbolAddress((void**)&n1, g_n1);
    cudaGetSymbolAddress((void**)&n2, g_n2);
    cudaGetSymbolAddress((void**)&qv, g_qv);
    cudaGetSymbolAddress((void**)&kb, g_k);
    cudaGetSymbolAddress((void**)&attn, g_attn);
    cudaGetSymbolAddress((void**)&ctx, g_ctx);
    cudaGetSymbolAddress((void**)&qq, g_qq);
    cudaGetSymbolAddress((void**)&akk, g_akk);
    cudaGetSymbolAddress((void**)&vrT, g_vrT);
    cudaGetSymbolAddress((void**)&tmp, g_tmp);
    cudaGetSymbolAddress((void**)&rectH, g_rectH);
    cudaGetSymbolAddress((void**)&xx, g_xx);
    cudaGetSymbolAddress((void**)&hdn, g_hdn);
    cudaGetSymbolAddress((void**)&h1, g_h1);
    cudaGetSymbolAddress((void**)&wt, g_wt);

    __half* n2x = n2;
    __half* n2a = n2 + (size_t)B_*N_*C_;
    const long zQ = (long)BH_*N_*HD_;
    const long zK = (long)CH_*N_*HD_;
    __half* qh = qq;
    __half* q2 = qq + zQ;
    __half* kh = akk;
    __half* k2 = akk + zK;

    // 0) weight transpose-convert + pad zeroing (single launch; pad rows 8 per block)
    int padBlocks = (BH_*N_ + BH_*HD_ + 7) / 8;
    transpose_all<<<TRN_BLKS + padBlocks, dim3(32, 8)>>>(Wqk, Wqk2, Wv, Wr_proj, W1, W2,
                                                         wt, tmp, vrT);

    // 1) LayerNorms
    ln_kernel<<<26, 128>>>(x, n1, g1, b1, 26, 26, 0, (long)T_*C_, 0);
    ln_kernel<<<26*N_, 128>>>(x + C_, n2, g2, b2, 26*N_, N_, (long)T_*C_, C_, 1);

    // 2) cls path
    rowgemm_cls<<<dim3(26, 12), 256>>>(n1, Wqv, Wk, qv, kb);
    attn_cls_kernel<<<B_, 384>>>(qv, kb, attn, ctx);
    rowgemm<<<dim3(B_, 6), 256>>>(ctx, Wq_proj, bq_proj, xx, C_, (long)T_*C_);

    // 3) head projections
    gemm_h<<<dim3(6, 25, 2), 256>>>(n2x, wt + OW_QK, nullptr, nullptr, nullptr, qq,
                                    B_*N_, C_, C_, C_, C_, 0, 1, 0, 147456, zQ);
    gemm_h64<<<dim3(6, 31, 2), 256>>>(n2a, wt + OW_QK, nullptr, nullptr, nullptr, akk,
                                      NC_*N_, C_, C_, C_, C_, 0, 1, 0, 147456, zK);
    gemm_h64<<<dim3(6, 49), 256>>>(n2x, wt + OW_V, nullptr, nullptr, nullptr, vrT,
                                   B_*N_, C_, C_, C_, C_, 0, 4, 0, 0, 0);

    // 4) fused rectified attention core -> tmp (proven R12 kernel)
    dim3 gf(2, 2, BH_);
    fused_attn3<<<gf, 256>>>(qh, kh, q2, k2, attn, tmp);

    // 5) rect = tmp @ vr -> rectH flat [bh][n][d]
    gemm_h64<<<dim3(1, 4, BH_), 256>>>(tmp, vrT, nullptr, nullptr, nullptr, rectH,
                                       N_, HD_, KP_, KP_, KP_, 0, 5,
                                       (long)N_*KP_, (long)HD_*KP_, 0);

    // 6) rect projection + residual -> xx rows 1..196
    gemm_h64<<<dim3(6, 49), 256>>>(rectH, wt + OW_R, br_proj, x, xx, nullptr,
                                   B_*N_, C_, C_, C_, C_, 0, 2, 0, 0, 0);

    // 7) MLP
    ln_kernel<<<B_*T_, 128>>>(xx, hdn, g3, b3, B_*T_, B_*T_, 0, C_, 1);
    gemm_h<<<dim3(24, 25), 256>>>(hdn, wt + OW_1, bm1, nullptr, nullptr, h1,
                                  B_*T_, 4*C_, C_, C_, C_, 1, 0, 0, 0, 0);
    gemm_h64<<<dim3(6, 50), 256>>>(h1, wt + OW_2, bm2, xx, outp, nullptr,
                                   B_*T_, C_, 4*C_, 4*C_, 4*C_, 0, 0, 0, 0, 0);

    // 8) anchors pass-through
    int n4 = NC_*T_*C_/4;
    copy_kernel<<<(n4 + 255)/256, 256>>>(x + (long)16*T_*C_, outp + (long)16*T_*C_, n4);
}